// round 16
// baseline (speedup 1.0000x reference)
#include <cuda_runtime.h>
#include <cuda_bf16.h>
#include <cstdint>
#include <cstddef>

// Problem constants
#define B_   256
#define S_   256
#define D_   1024
#define P_   512
#define SH   254
#define NROWS (B_*SH)       // 65024
#define EPS_ 1e-7f

// Scratch (__device__ globals: allocation-free rule)
__device__ float g_bias[B_*P_];
__device__ float g_spart[4*NROWS];                    // per-N-block score partials
__device__ int   g_mask_mode;
__device__ __align__(1024) __nv_bfloat16 g_w1t[(size_t)P_*D_];    // proj_head^T bf16
__device__ __align__(1024) __nv_bfloat16 g_h0t[(size_t)P_*P_];    // hidden0^T bf16
__device__ __align__(1024) __nv_bfloat16 g_h1t[(size_t)P_*P_];    // hidden1^T bf16
__device__ __align__(1024) __nv_bfloat16 g_c0[(size_t)NROWS*P_];  // act after stage 1
__device__ __align__(1024) __nv_bfloat16 g_c1[(size_t)NROWS*P_];  // act after stage 2

__device__ __forceinline__ float fast_tanh(float x) {
    float y; asm("tanh.approx.f32 %0, %1;" : "=f"(y) : "f"(x)); return y;
}
__device__ __forceinline__ uint32_t smem_u32(const void* p) {
    uint32_t a;
    asm("{ .reg .u64 t; cvta.to.shared.u64 t, %1; cvt.u32.u64 %0, t; }" : "=r"(a) : "l"(p));
    return a;
}

// ---------------------------------------------------------------------------
// Fused pre-pass (no convert role anymore):
//   blocks [0,128)   : bias, 8 batches/block
//   blocks [128,640) : weight transpose -> bf16, 2 tiles/block
//   block  640       : mask dtype probe
// ---------------------------------------------------------------------------
#define PRE_SMEM (20480 * 4)   // 80KB

__global__ void __launch_bounds__(512) prepass_kernel(
    const float*  __restrict__ x,
    const float*  __restrict__ wp,
    const float*  __restrict__ wc,
    const float*  __restrict__ w_head,
    const float*  __restrict__ hid,
    const unsigned int* __restrict__ mask_w)
{
    extern __shared__ __align__(16) float dsm[];
    const int bx = blockIdx.x;
    const int tid = threadIdx.x;

    if (bx < 128) {
        float* sP  = dsm;            // [8][1024]
        float* sC  = dsm + 8192;     // [8][1024]
        float* red = dsm + 16384;    // [4][8][128]
        const int pblk = bx >> 5, bblk = bx & 31;
        const int b0 = bblk * 8;

        #pragma unroll
        for (int it = 0; it < 8; it++) {
            int idx  = tid + it * 512;
            int row  = idx >> 8;
            int col4 = idx & 255;
            int bb   = b0 + (row >> 1);
            int which = row & 1;
            const float* src = x + ((size_t)bb * S_ + (S_ - 2) + which) * D_;
            float4 v = *(const float4*)(src + col4 * 4);
            float* dst = (which ? sC : sP) + (row >> 1) * 1024;
            *(float4*)(dst + col4 * 4) = v;
        }
        __syncthreads();

        const int pl = tid & 127;
        const int q  = tid >> 7;
        const int p  = pblk * 128 + pl;
        const int d0 = q * 256;

        float acc[8];
        #pragma unroll
        for (int j = 0; j < 8; j++) acc[j] = 0.f;
        #pragma unroll 4
        for (int d = d0; d < d0 + 256; d++) {
            float a = wp[(size_t)d * P_ + p];
            float c = wc[(size_t)d * P_ + p];
            #pragma unroll
            for (int j = 0; j < 8; j++)
                acc[j] += sP[j * 1024 + d] * a + sC[j * 1024 + d] * c;
        }
        #pragma unroll
        for (int j = 0; j < 8; j++) red[(q * 8 + j) * 128 + pl] = acc[j];
        __syncthreads();
        if (q == 0) {
            #pragma unroll
            for (int j = 0; j < 8; j++) {
                float v = red[(0 + j) * 128 + pl] + red[(8 + j) * 128 + pl]
                        + red[(16 + j) * 128 + pl] + red[(24 + j) * 128 + pl];
                g_bias[(size_t)(b0 + j) * P_ + p] = v;
            }
        }
    } else if (bx < 640) {
        const int tl = tid & 255, tsel = tid >> 8;
        const int t = (bx - 128) * 2 + tsel;
        int z, u;
        if (t < 512)      { z = 0; u = t; }
        else if (t < 768) { z = 1; u = t - 512; }
        else              { z = 2; u = t - 768; }
        const int K = (z == 0) ? D_ : P_;
        const int pb = u & 15, kb = u >> 4;
        const float* src = (z == 0) ? w_head : (hid + (size_t)(z - 1) * P_ * P_);
        __nv_bfloat16* dst = (z == 0) ? g_w1t : ((z == 1) ? g_h0t : g_h1t);

        float* ts = dsm + tsel * 1056;
        const int k0 = kb * 32, n0 = pb * 32;
        const int tx = tl & 31, ty = tl >> 5;
        #pragma unroll
        for (int i = 0; i < 32; i += 8)
            ts[(ty + i) * 33 + tx] = src[(size_t)(k0 + ty + i) * P_ + n0 + tx];
        __syncthreads();
        #pragma unroll
        for (int i = 0; i < 32; i += 8)
            dst[(size_t)(n0 + ty + i) * K + k0 + tx] = __float2bfloat16_rn(ts[tx * 33 + ty + i]);
    } else {
        __shared__ int s01, sf;
        if (tid == 0) { s01 = 1; sf = 1; }
        __syncthreads();
        bool ok01 = true, okf = true;
        #pragma unroll 4
        for (int it = 0; it < 32; it++) {
            unsigned int v = mask_w[tid + it * 512];
            if (v > 1u) ok01 = false;
            if (v != 0u && v != 0x3F800000u) okf = false;
        }
        if (!ok01) atomicAnd(&s01, 0);
        if (!okf)  atomicAnd(&sf, 0);
        __syncthreads();
        if (tid == 0) g_mask_mode = s01 ? 0 : (sf ? 1 : 2);
    }
}

// ---------------------------------------------------------------------------
// Stage-1 GEMM, fp32 A path: x fp32 -> cp.async staging -> in-kernel bf16
// convert -> swizzled Abf16 -> ldmatrix/MMA (unchanged math, rn rounding
// identical to the old standalone convert).
// CTA 128 threads (2M x 2N warps, warp tile 64x64), tile 128x128, BK=64, T=16.
// smem: staging fp32 2 x 32KB @0 | Abf16 16KB @65536 | B bf16 2 x 16KB @81920
//       = 112KB -> 2 CTAs/SM (224KB).
// ---------------------------------------------------------------------------
#define G1SMEM 114688

__global__ void __launch_bounds__(128, 2) gemm1_f32(
    const float* __restrict__ X,
    const __nv_bfloat16* __restrict__ BT,
    __nv_bfloat16* __restrict__ Cout)
{
    constexpr int T = 16;          // K=1024, BK=64
    extern __shared__ __align__(1024) char smem[];
    const uint32_t sb = smem_u32(smem);
    const int tid = threadIdx.x, lane = tid & 31, wid = tid >> 5;
    const int wm = wid >> 1, wn = wid & 1;
    const int N0 = blockIdx.x * 128, R0 = blockIdx.y * 128;

    // ---- A fill mapping: 2048 16B-chunks; thread: ca = tid&15 (chunk in 256B
    // row), rows ra + 8j (j<16). Swizzle term constant per thread (8j ≡ 0 mod 8).
    const int ca = tid & 15, ra = tid >> 4;
    const uint32_t sA0 = (uint32_t)(ra * 256 + ((ca ^ (ra & 7)) << 4));
    uint32_t aoff[16];   // byte offsets into X (x < 4GB so u32 ok)
    #pragma unroll
    for (int j = 0; j < 16; j++) {
        int r = R0 + ra + 8 * j;
        int b = r / SH; int s2 = r - b * SH;
        aoff[j] = (uint32_t)(((b * S_ + s2) * D_ + ca * 4) * 4);
    }
    // ---- B fill mapping (bf16, rows of 128B) — as previous rounds
    const int rb = tid >> 3, cb = tid & 7;
    const uint32_t sB0 = (uint32_t)(rb * 128 + ((cb ^ (rb & 7)) << 4));
    const uint32_t boff0 = (uint32_t)(((N0 + rb) * D_ + cb * 8) * 2);
    const char* Xb = (const char*)X;
    const char* Bb = (const char*)BT;

    auto fill = [&](int slot, int kt) {
        uint32_t sbase = sb + slot * 32768;
        uint32_t koffA = (uint32_t)kt * 256;   // 64 fp32 = 256B
        #pragma unroll
        for (int j = 0; j < 16; j++)
            asm volatile("cp.async.cg.shared.global [%0], [%1], 16;"
                :: "r"(sbase + sA0 + j * 2048), "l"(Xb + aoff[j] + koffA) : "memory");
        uint32_t bbase = sb + 81920 + slot * 16384;
        uint32_t koffB = (uint32_t)kt * 128;   // 64 bf16 = 128B
        #pragma unroll
        for (int i = 0; i < 8; i++)
            asm volatile("cp.async.cg.shared.global [%0], [%1], 16;"
                :: "r"(bbase + sB0 + i * 2048),
                   "l"(Bb + boff0 + (uint32_t)i * (16u * D_ * 2u) + koffB) : "memory");
        asm volatile("cp.async.commit_group;" ::: "memory");
    };

    // convert: staging[slot] fp32 -> Abf16 (swizzled). thread: fixed fp32
    // chunk c = tid&15, rows (tid>>4) + 8j. 4-phase reads / 2-phase writes.
    const int cc2 = tid & 15, rr2 = tid >> 4;
    auto convert = [&](int slot) {
        #pragma unroll
        for (int j = 0; j < 16; j++) {
            int r = rr2 + 8 * j;
            uint32_t roff = (uint32_t)(slot * 32768 + r * 256 + ((cc2 ^ (r & 7)) << 4));
            float4 v = *(const float4*)(smem + roff);
            __nv_bfloat162 lo = __floats2bfloat162_rn(v.x, v.y);
            __nv_bfloat162 hi = __floats2bfloat162_rn(v.z, v.w);
            uint2 o; o.x = *(uint32_t*)&lo; o.y = *(uint32_t*)&hi;
            uint32_t woff = (uint32_t)(65536 + r * 128 + (((cc2 >> 1) ^ (r & 7)) << 4) + (cc2 & 1) * 8);
            *(uint2*)(smem + woff) = o;
        }
    };

    float acc[4][8][4];
    #pragma unroll
    for (int a = 0; a < 4; a++)
        #pragma unroll
        for (int b = 0; b < 8; b++)
            #pragma unroll
            for (int c = 0; c < 4; c++) acc[a][b][c] = 0.f;

    fill(0, 0);
    fill(1, 1);

    const int lrow = lane & 15;
    const int lhalf = lane >> 4;
    const int lswz = lrow & 7;

    for (int t = 0; t < T; t++) {
        if (t < T - 1) asm volatile("cp.async.wait_group 1;" ::: "memory");
        else           asm volatile("cp.async.wait_group 0;" ::: "memory");
        __syncthreads();
        convert(t & 1);
        __syncthreads();

        const uint32_t ab = sb + 65536;
        const uint32_t bbs = sb + 81920 + (t & 1) * 16384;
        #pragma unroll
        for (int kk = 0; kk < 4; kk++) {
            const uint32_t coff = (uint32_t)(((kk * 2 + lhalf) ^ lswz) << 4);
            uint32_t ar[4][4], br[4][4];
            #pragma unroll
            for (int mi = 0; mi < 4; mi++) {
                uint32_t addr = ab + (uint32_t)((wm * 64 + mi * 16 + lrow) * 128) + coff;
                asm volatile("ldmatrix.sync.aligned.m8n8.x4.shared.b16 {%0,%1,%2,%3}, [%4];"
                    : "=r"(ar[mi][0]), "=r"(ar[mi][1]), "=r"(ar[mi][2]), "=r"(ar[mi][3])
                    : "r"(addr));
            }
            #pragma unroll
            for (int np = 0; np < 4; np++) {
                uint32_t addr = bbs + (uint32_t)((wn * 64 + np * 16 + lrow) * 128) + coff;
                asm volatile("ldmatrix.sync.aligned.m8n8.x4.shared.b16 {%0,%1,%2,%3}, [%4];"
                    : "=r"(br[np][0]), "=r"(br[np][1]), "=r"(br[np][2]), "=r"(br[np][3])
                    : "r"(addr));
            }
            #pragma unroll
            for (int mi = 0; mi < 4; mi++)
                #pragma unroll
                for (int nj = 0; nj < 8; nj++) {
                    uint32_t b0 = br[nj >> 1][nj & 1];
                    uint32_t b1 = br[nj >> 1][(nj & 1) + 2];
                    asm volatile(
                        "mma.sync.aligned.m16n8k16.row.col.f32.bf16.bf16.f32 "
                        "{%0,%1,%2,%3}, {%4,%5,%6,%7}, {%8,%9}, {%0,%1,%2,%3};"
                        : "+f"(acc[mi][nj][0]), "+f"(acc[mi][nj][1]),
                          "+f"(acc[mi][nj][2]), "+f"(acc[mi][nj][3])
                        : "r"(ar[mi][0]), "r"(ar[mi][1]), "r"(ar[mi][2]), "r"(ar[mi][3]),
                          "r"(b0), "r"(b1));
                }
        }
        __syncthreads();
        if (t + 2 < T) fill(t & 1, t + 2);
    }

    // ---- epilogue: +bias, tanh -> bf16 c0 ----
    const int r4 = lane >> 2, l2 = (lane & 3) * 2;
    #pragma unroll
    for (int mi = 0; mi < 4; mi++)
        #pragma unroll
        for (int h = 0; h < 2; h++) {
            int m = R0 + wm * 64 + mi * 16 + r4 + h * 8;
            const float* brow_ = g_bias + (size_t)(m / SH) * P_;
            #pragma unroll
            for (int nj = 0; nj < 8; nj++) {
                int n = N0 + wn * 64 + nj * 8 + l2;
                float v0 = acc[mi][nj][h * 2 + 0];
                float v1 = acc[mi][nj][h * 2 + 1];
                float2 bv = *(const float2*)(brow_ + n);
                v0 += bv.x; v1 += bv.y;
                __nv_bfloat162 o = __floats2bfloat162_rn(fast_tanh(v0), fast_tanh(v1));
                *(uint32_t*)(Cout + (size_t)m * P_ + n) = *(uint32_t*)&o;
            }
        }
}

// ---------------------------------------------------------------------------
// bf16 GEMM stages 2/3 (unchanged from R13/14). CTA 128 thr, tile 128x128,
// warp 64x64, BK=64, 3-stage cp.async, 96KB -> 2 CTAs/SM.
// EPI: 1 = tanh -> bf16 Cout ; 2 = tanh + scorer partial
// ---------------------------------------------------------------------------
#define GSMEM 98304

template<int K, int EPI>
__global__ void __launch_bounds__(128, 2) gemm_bf16(
    const __nv_bfloat16* __restrict__ A,
    const __nv_bfloat16* __restrict__ BT,
    const float* __restrict__ scorer,
    __nv_bfloat16* __restrict__ Cout)
{
    constexpr int T = K / 64;
    extern __shared__ __align__(1024) char smem[];
    const uint32_t sb = smem_u32(smem);
    const int tid = threadIdx.x, lane = tid & 31, wid = tid >> 5;
    const int wm = wid >> 1, wn = wid & 1;
    const int N0 = blockIdx.x * 128, R0 = blockIdx.y * 128;

    const int r0 = tid >> 3, cc = tid & 7;
    const uint32_t sA0 = (uint32_t)(r0 * 128 + ((cc ^ (r0 & 7)) << 4));
    uint32_t aoff[8];
    #pragma unroll
    for (int i = 0; i < 8; i++) {
        int r = R0 + r0 + i * 16;
        aoff[i] = (uint32_t)((r * K + cc * 8) * 2);
    }
    const uint32_t boff0 = (uint32_t)(((N0 + r0) * K + cc * 8) * 2);
    const char* Ab = (const char*)A;
    const char* Bb = (const char*)BT;

    auto fill = [&](int slot, int kt) {
        uint32_t base = sb + slot * 32768;
        uint32_t koff = (uint32_t)kt * 128;
        #pragma unroll
        for (int i = 0; i < 8; i++)
            asm volatile("cp.async.cg.shared.global [%0], [%1], 16;"
                :: "r"(base + sA0 + i * 2048), "l"(Ab + aoff[i] + koff) : "memory");
        #pragma unroll
        for (int i = 0; i < 8; i++)
            asm volatile("cp.async.cg.shared.global [%0], [%1], 16;"
                :: "r"(base + 16384 + sA0 + i * 2048),
                   "l"(Bb + boff0 + (uint32_t)i * (16u * K * 2u) + koff) : "memory");
        asm volatile("cp.async.commit_group;" ::: "memory");
    };

    float acc[4][8][4];
    #pragma unroll
    for (int a = 0; a < 4; a++)
        #pragma unroll
        for (int b = 0; b < 8; b++)
            #pragma unroll
            for (int c = 0; c < 4; c++) acc[a][b][c] = 0.f;

    fill(0, 0);
    fill(1, 1);
    fill(2, 2);

    const int lrow = lane & 15;
    const int lhalf = lane >> 4;
    const int lswz = lrow & 7;

    for (int t = 0; t < T; t++) {
        int rem = T - 1 - t;
        if (rem >= 2)      asm volatile("cp.async.wait_group 2;" ::: "memory");
        else if (rem == 1) asm volatile("cp.async.wait_group 1;" ::: "memory");
        else               asm volatile("cp.async.wait_group 0;" ::: "memory");
        __syncthreads();

        const int slot = t % 3;
        const uint32_t ab = sb + slot * 32768;
        const uint32_t bbs = ab + 16384;
        #pragma unroll
        for (int kk = 0; kk < 4; kk++) {
            const uint32_t coff = (uint32_t)(((kk * 2 + lhalf) ^ lswz) << 4);
            uint32_t ar[4][4], br[4][4];
            #pragma unroll
            for (int mi = 0; mi < 4; mi++) {
                uint32_t addr = ab + (uint32_t)((wm * 64 + mi * 16 + lrow) * 128) + coff;
                asm volatile("ldmatrix.sync.aligned.m8n8.x4.shared.b16 {%0,%1,%2,%3}, [%4];"
                    : "=r"(ar[mi][0]), "=r"(ar[mi][1]), "=r"(ar[mi][2]), "=r"(ar[mi][3])
                    : "r"(addr));
            }
            #pragma unroll
            for (int np = 0; np < 4; np++) {
                uint32_t addr = bbs + (uint32_t)((wn * 64 + np * 16 + lrow) * 128) + coff;
                asm volatile("ldmatrix.sync.aligned.m8n8.x4.shared.b16 {%0,%1,%2,%3}, [%4];"
                    : "=r"(br[np][0]), "=r"(br[np][1]), "=r"(br[np][2]), "=r"(br[np][3])
                    : "r"(addr));
            }
            #pragma unroll
            for (int mi = 0; mi < 4; mi++)
                #pragma unroll
                for (int nj = 0; nj < 8; nj++) {
                    uint32_t b0 = br[nj >> 1][nj & 1];
                    uint32_t b1 = br[nj >> 1][(nj & 1) + 2];
                    asm volatile(
                        "mma.sync.aligned.m16n8k16.row.col.f32.bf16.bf16.f32 "
                        "{%0,%1,%2,%3}, {%4,%5,%6,%7}, {%8,%9}, {%0,%1,%2,%3};"
                        : "+f"(acc[mi][nj][0]), "+f"(acc[mi][nj][1]),
                          "+f"(acc[mi][nj][2]), "+f"(acc[mi][nj][3])
                        : "r"(ar[mi][0]), "r"(ar[mi][1]), "r"(ar[mi][2]), "r"(ar[mi][3]),
                          "r"(b0), "r"(b1));
                }
        }
        __syncthreads();
        if (t + 3 < T) fill(slot, t + 3);
    }

    // ---- epilogue ----
    const int r4 = lane >> 2, l2 = (lane & 3) * 2;
    if (EPI < 2) {
        #pragma unroll
        for (int mi = 0; mi < 4; mi++)
            #pragma unroll
            for (int h = 0; h < 2; h++) {
                int m = R0 + wm * 64 + mi * 16 + r4 + h * 8;
                #pragma unroll
                for (int nj = 0; nj < 8; nj++) {
                    int n = N0 + wn * 64 + nj * 8 + l2;
                    float v0 = acc[mi][nj][h * 2 + 0];
                    float v1 = acc[mi][nj][h * 2 + 1];
                    __nv_bfloat162 o = __floats2bfloat162_rn(fast_tanh(v0), fast_tanh(v1));
                    *(uint32_t*)(Cout + (size_t)m * P_ + n) = *(uint32_t*)&o;
                }
            }
    } else {
        __syncthreads();
        float* red = (float*)smem;
        #pragma unroll
        for (int mi = 0; mi < 4; mi++)
            #pragma unroll
            for (int h = 0; h < 2; h++) {
                float sum = 0.f;
                #pragma unroll
                for (int nj = 0; nj < 8; nj++) {
                    int n = N0 + wn * 64 + nj * 8 + l2;
                    float v0 = fast_tanh(acc[mi][nj][h * 2 + 0]);
                    float v1 = fast_tanh(acc[mi][nj][h * 2 + 1]);
                    sum += v0 * __ldg(scorer + n) + v1 * __ldg(scorer + n + 1);
                }
                sum += __shfl_xor_sync(0xffffffffu, sum, 1);
                sum += __shfl_xor_sync(0xffffffffu, sum, 2);
                if ((lane & 3) == 0)
                    red[wn * 128 + wm * 64 + mi * 16 + r4 + h * 8] = sum;
            }
        __syncthreads();
        float tot = red[tid] + red[128 + tid];
        g_spart[(size_t)blockIdx.x * NROWS + R0 + tid] = tot;
    }
}

// ---------------------------------------------------------------------------
// masked softmax over s per batch; sums the 4 N-block score partials.
// ---------------------------------------------------------------------------
__global__ void __launch_bounds__(256) softmax_kernel(
    const void* __restrict__ mask_raw, float* __restrict__ out)
{
    __shared__ float red[256];
    const int b = blockIdx.x;
    const int s = threadIdx.x;
    const int mode = g_mask_mode;
    float e = 0.f;
    if (s < SH) {
        bool m;
        int idx = b * S_ + s;
        if (mode == 0)      m = ((const int*)mask_raw)[idx] != 0;
        else if (mode == 1) m = ((const float*)mask_raw)[idx] != 0.f;
        else                m = ((const unsigned char*)mask_raw)[idx] != 0;
        int r = b * SH + s;
        float sc = g_spart[r] + g_spart[NROWS + r] + g_spart[2 * NROWS + r] + g_spart[3 * NROWS + r];
        e = m ? expf(sc) : 0.f;
    }
    red[s] = e;
    __syncthreads();
    #pragma unroll
    for (int o = 128; o > 0; o >>= 1) {
        if (s < o) red[s] += red[s + o];
        __syncthreads();
    }
    float inv = 1.f / (red[0] + EPS_);
    if (s < SH) out[b * SH + s] = e * inv;
}

// ---------------------------------------------------------------------------
extern "C" void kernel_launch(void* const* d_in, const int* in_sizes, int n_in,
                              void* d_out, int out_size)
{
    // Resolve inputs by element count (robust to metadata ordering).
    int xi = -1, si = -1, mi = -1;
    int q[4] = {-1, -1, -1, -1};
    int nq = 0;
    for (int i = 0; i < n_in; i++) {
        long long sz = in_sizes[i];
        if (sz == (long long)B_ * S_ * D_)      xi = i;
        else if (sz == P_)                      si = i;
        else if (sz == (long long)B_ * S_)      mi = i;
        else if (sz == (long long)D_ * P_ && nq < 4) q[nq++] = i;
    }
    if (xi < 0 || si < 0 || mi < 0 || nq != 4) {
        xi = 0; q[0] = 1; q[1] = 2; q[2] = 3; q[3] = 4; si = 5; mi = 6;
    }
    const float *w_head, *w_prep, *w_child, *hid;
    if (xi == 0) {
        w_head = (const float*)d_in[q[0]];
        w_prep = (const float*)d_in[q[1]];
        w_child = (const float*)d_in[q[2]];
        hid    = (const float*)d_in[q[3]];
    } else {
        hid    = (const float*)d_in[q[0]];
        w_child = (const float*)d_in[q[1]];
        w_head = (const float*)d_in[q[2]];
        w_prep = (const float*)d_in[q[3]];
    }
    const float* x = (const float*)d_in[xi];
    const float* scorer = (const float*)d_in[si];
    const void* mask = d_in[mi];
    float* out = (float*)d_out;

    __nv_bfloat16 *w1t_p, *h0t_p, *h1t_p, *c0_p, *c1_p;
    cudaGetSymbolAddress((void**)&w1t_p, g_w1t);
    cudaGetSymbolAddress((void**)&h0t_p, g_h0t);
    cudaGetSymbolAddress((void**)&h1t_p, g_h1t);
    cudaGetSymbolAddress((void**)&c0_p,  g_c0);
    cudaGetSymbolAddress((void**)&c1_p,  g_c1);

    cudaFuncSetAttribute(prepass_kernel,   cudaFuncAttributeMaxDynamicSharedMemorySize, PRE_SMEM);
    cudaFuncSetAttribute(gemm1_f32,        cudaFuncAttributeMaxDynamicSharedMemorySize, G1SMEM);
    cudaFuncSetAttribute(gemm_bf16<512,1>, cudaFuncAttributeMaxDynamicSharedMemorySize, GSMEM);
    cudaFuncSetAttribute(gemm_bf16<512,2>, cudaFuncAttributeMaxDynamicSharedMemorySize, GSMEM);

    prepass_kernel<<<641, 512, PRE_SMEM>>>(x, w_prep, w_child, w_head, hid,
                                           (const unsigned int*)mask);

    gemm1_f32<<<dim3(4, NROWS/128), 128, G1SMEM>>>(x, w1t_p, c0_p);
    gemm_bf16<512,1><<<dim3(4, NROWS/128), 128, GSMEM>>>(c0_p, h0t_p, scorer, c1_p);
    gemm_bf16<512,2><<<dim3(4, NROWS/128), 128, GSMEM>>>(c1_p, h1t_p, scorer, nullptr);

    softmax_kernel<<<B_, 256>>>(mask, out);
}